// round 12
// baseline (speedup 1.0000x reference)
#include <cuda_runtime.h>
#include <cuda_bf16.h>

// x  : (1, 64, 28, 28) fp32 -> (2 groups o, 32 ch j, 28 n, 28 m)
// w1 : (128, 9),  w2 : (32, 7, 9)
// out: (1, 256, 28, 28), channel = o*128 + c, rolled +1 along height.
//
// t4[o,n,m,i]         = sum_{j,k} x[o*32+j, n, m+k-3] * w2[j,k,i]
// out[o,c,(n+1)%28,m] = sum_i w1[c,i] * t4[o,n,m,i]
//
// Grid 112 = (og, n, m-half). t4 thread = (j-quarter, i, m-pair): 252 threads,
// 112 MACs each via FFMA2 (even-k packed) + scalar odd-k. 2 warps/SMSP in
// every phase (the R7 trap avoided). Phase 2 c-major, w1 in registers.

#define NTHREADS 256

union UF2 {
    unsigned long long u;
    float2 f;
};

#define FFMA2(acc, a, b) \
    asm("fma.rn.f32x2 %0, %1, %2, %0;" : "+l"(acc) : "l"(a), "l"(b))

__global__ __launch_bounds__(NTHREADS)
void fused_unfold_einsum_kernel(const float* __restrict__ x,
                                const float* __restrict__ w1,
                                const float* __restrict__ w2,
                                float* __restrict__ out) {
    __shared__ __align__(16) float  xs[32][20];   // 14-wide half tile + 3 halo
    __shared__ __align__(16) float  w2d[9 * 516]; // [i][j*16 + k*2] = (w,w) pairs
    __shared__ __align__(16) float  t4s[14 * 12]; // [m_local][i], stride 12
    __shared__ __align__(16) float2 t4p[3 * 63];  // quarter partials [q-1][t]

    const int tid    = threadIdx.x;
    const int b      = blockIdx.x;      // 0..111
    const int og     = b / 56;
    const int r      = b - og * 56;
    const int n      = r >> 1;
    const int mh     = r & 1;
    const int m_base = mh * 14;

    // --- Prefetch this thread's w1 row to registers (phase 2).
    const int c    = tid & 127;
    const int mseg = tid >> 7;
    float w1r[9];
    #pragma unroll
    for (int ii = 0; ii < 9; ++ii)
        w1r[ii] = __ldg(&w1[c * 9 + ii]);

    // --- Stage w2 as duplicated (w,w) pairs: w2d[i*516 + j*16 + k*2 (+1)]
    #pragma unroll
    for (int idx = tid; idx < 2016; idx += NTHREADS) {   // 32*7*9
        const int rr = idx / 9;         // j*7 + k
        const int i  = idx - rr * 9;
        const int j  = rr / 7;
        const int k  = rr - j * 7;
        const float v = w2[idx];
        const int d = i * 516 + j * 16 + k * 2;
        w2d[d]     = v;
        w2d[d + 1] = v;
    }
    // --- Stage x half-row slab with zero halo: cols = m_base-3 .. m_base+16
    #pragma unroll
    for (int idx = tid; idx < 32 * 20; idx += NTHREADS) {
        const int j   = idx / 20;
        const int col = idx - j * 20;
        const int m   = m_base - 3 + col;
        float v = 0.0f;
        if (m >= 0 && m < 28)
            v = x[((og * 32 + j) * 28 + n) * 28 + m];
        xs[j][col] = v;
    }
    __syncthreads();

    // --- t4 partials: thread = (j-quarter q, i, m-pair). 252 threads.
    float r0 = 0.f, r1 = 0.f;
    int t = 0, i = 0, m0 = 0;
    if (tid < 252) {
        const int q  = tid / 63;
        t  = tid - q * 63;
        i  = t / 7;
        const int mp = t - i * 7;
        m0 = mp * 2;                    // local m, even -> 8B-aligned xs reads
        const int jb = q * 8;

        UF2 A;                          // packed acc (m0, m1), even k
        A.u = 0;
        float s0 = 0.f, s1 = 0.f;       // odd-k scalar accs for m0 / m1

        #pragma unroll
        for (int j = 0; j < 8; ++j) {
            const int row = jb + j;
            const unsigned long long* __restrict__ xp =
                reinterpret_cast<const unsigned long long*>(&xs[row][m0]);
            const unsigned long long* __restrict__ wp =
                reinterpret_cast<const unsigned long long*>(&w2d[i * 516 + row * 16]);
            UF2 P0, P1, P2, P3;         // x[m0 .. m0+7] as aligned pairs
            P0.u = xp[0]; P1.u = xp[1]; P2.u = xp[2]; P3.u = xp[3];
            const unsigned long long W0 = wp[0], W2 = wp[2],
                                     W4 = wp[4], W6 = wp[6];
            UF2 W1s, W3s, W5s;          // odd weights, scalar view
            W1s.u = wp[1]; W3s.u = wp[3]; W5s.u = wp[5];

            // even k: (x[m0+k], x[m0+1+k]) are the aligned pairs
            FFMA2(A.u, P0.u, W0);       // k=0
            FFMA2(A.u, P1.u, W2);       // k=2
            FFMA2(A.u, P2.u, W4);       // k=4
            FFMA2(A.u, P3.u, W6);       // k=6
            // odd k: components of already-loaded pairs
            s0 = fmaf(P0.f.y, W1s.f.x, s0);  s1 = fmaf(P1.f.x, W1s.f.x, s1); // k=1
            s0 = fmaf(P1.f.y, W3s.f.x, s0);  s1 = fmaf(P2.f.x, W3s.f.x, s1); // k=3
            s0 = fmaf(P2.f.y, W5s.f.x, s0);  s1 = fmaf(P3.f.x, W5s.f.x, s1); // k=5
        }
        r0 = A.f.x + s0;
        r1 = A.f.y + s1;
        if (q > 0)
            t4p[(q - 1) * 63 + t] = make_float2(r0, r1);
    }
    __syncthreads();

    // --- Recombine the 4 j-quarters (threads 0..62 hold quarter 0).
    if (tid < 63) {
        const float2 u1 = t4p[t];
        const float2 u2 = t4p[63 + t];
        const float2 u3 = t4p[126 + t];
        t4s[(m0 + 0) * 12 + i] = r0 + u1.x + u2.x + u3.x;
        t4s[(m0 + 1) * 12 + i] = r1 + u1.y + u2.y + u3.y;
    }
    __syncthreads();

    // --- Phase 2, c-major: w1 in regs, t4s via broadcast LDS.128,
    //     2 m's per 8B-aligned STG.64. mseg0: m 0..7, mseg1: m 8..13.
    const int nout   = (n + 1) % 28;    // jnp.roll(y, +1, axis=2)
    const int mstart = mseg ? 8 : 0;
    const int ngrp   = mseg ? 3 : 4;
    float* __restrict__ orow =
        &out[((og * 128 + c) * 28 + nout) * 28 + m_base];

    #pragma unroll
    for (int gp = 0; gp < 4; ++gp) {
        if (gp < ngrp) {                // warp-uniform predicate
            float o2[2];
            #pragma unroll
            for (int qq = 0; qq < 2; ++qq) {
                const int m = mstart + gp * 2 + qq;
                const float4* __restrict__ tv =
                    reinterpret_cast<const float4*>(&t4s[m * 12]);
                const float4 v0 = tv[0], v1 = tv[1], v2 = tv[2];
                float acc = v0.x * w1r[0];
                acc = fmaf(v0.y, w1r[1], acc);
                acc = fmaf(v0.z, w1r[2], acc);
                acc = fmaf(v0.w, w1r[3], acc);
                acc = fmaf(v1.x, w1r[4], acc);
                acc = fmaf(v1.y, w1r[5], acc);
                acc = fmaf(v1.z, w1r[6], acc);
                acc = fmaf(v1.w, w1r[7], acc);
                acc = fmaf(v2.x, w1r[8], acc);
                o2[qq] = acc;
            }
            *reinterpret_cast<float2*>(&orow[mstart + gp * 2]) =
                make_float2(o2[0], o2[1]);
        }
    }
}

extern "C" void kernel_launch(void* const* d_in, const int* in_sizes, int n_in,
                              void* d_out, int out_size) {
    const float* x  = (const float*)d_in[0];
    const float* w1 = (const float*)d_in[1];
    const float* w2 = (const float*)d_in[2];
    float* out = (float*)d_out;
    (void)in_sizes; (void)n_in; (void)out_size;

    fused_unfold_einsum_kernel<<<112, NTHREADS>>>(x, w1, w2, out);
}

// round 13
// speedup vs baseline: 1.1278x; 1.1278x over previous
#include <cuda_runtime.h>
#include <cuda_bf16.h>

// x  : (1, 64, 28, 28) fp32 -> (2 groups o, 32 ch j, 28 n, 28 m)
// w1 : (128, 9),  w2 : (32, 7, 9)
// out: (1, 256, 28, 28), channel = o*128 + c, rolled +1 along height.
//
// t4[o,n,m,i]         = sum_{j,k} x[o*32+j, n, m+k-3] * w2[j,k,i]
// out[o,c,(n+1)%28,m] = sum_i w1[c,i] * t4[o,n,m,i]
//
// Grid 112 = (og, n, m-half). 288 threads: t4 warp = i (9 warps), lane =
// (j-quarter q, m-pair mp). w2 staged VERBATIM (no transform; raw-layout
// reads are conflict-free by construction). Quarter reduce via shfl_down
// (no partials smem, only 2 barriers). Phase 2: c-major, w1 in registers.

#define NTHREADS 288

__global__ __launch_bounds__(NTHREADS)
void fused_unfold_einsum_kernel(const float* __restrict__ x,
                                const float* __restrict__ w1,
                                const float* __restrict__ w2,
                                float* __restrict__ out) {
    __shared__ __align__(16) float xs[32][20];   // 14-wide half tile + 3 halo
    __shared__ __align__(16) float w2s[2016];    // w2 verbatim: [(j*7+k)*9 + i]
    __shared__ __align__(16) float t4s[14 * 12]; // [m_local][i], stride 12

    const int tid    = threadIdx.x;
    const int b      = blockIdx.x;      // 0..111
    const int og     = b / 56;
    const int r      = b - og * 56;
    const int n      = r >> 1;
    const int mh     = r & 1;
    const int m_base = mh * 14;

    // --- Prefetch this thread's w1 row to registers (phase 2; tid>=256 redundant).
    const int c    = tid & 127;
    const int mseg = tid >> 7;          // phase-2 threads: 0 or 1
    float w1r[9];
    #pragma unroll
    for (int ii = 0; ii < 9; ++ii)
        w1r[ii] = __ldg(&w1[c * 9 + ii]);

    // --- Stage w2 verbatim: 2016 floats = 504 float4, no address transform.
    {
        const float4* __restrict__ src = reinterpret_cast<const float4*>(w2);
        float4* __restrict__ dst = reinterpret_cast<float4*>(w2s);
        #pragma unroll
        for (int idx = tid; idx < 504; idx += NTHREADS)
            dst[idx] = src[idx];
    }
    // --- Stage x half-row slab with zero halo: cols = m_base-3 .. m_base+16
    #pragma unroll
    for (int idx = tid; idx < 32 * 20; idx += NTHREADS) {
        const int j   = idx / 20;
        const int col = idx - j * 20;
        const int m   = m_base - 3 + col;
        float v = 0.0f;
        if (m >= 0 && m < 28)
            v = x[((og * 32 + j) * 28 + n) * 28 + m];
        xs[j][col] = v;
    }
    __syncthreads();

    // --- t4: warp = i (9 warps), lane = (q, mp). j = q + 4*jj (interleaved
    //     quarters). Weight LDS: 4 distinct addrs 63 words apart -> distinct
    //     banks + broadcast. Lanes 28..31 duplicate q=0 work (discarded).
    const int i    = tid >> 5;          // warp id = i, 0..8
    const int lane = tid & 31;
    {
        const int lq = lane / 7;
        const int q  = lq & 3;          // lanes 28..31 -> q=0 (dup, unused)
        const int mp = lane - lq * 7;   // 0..6 (lanes 28..31: 0..3)
        const int m0 = mp * 2;          // even -> 8B-aligned xs reads

        float r0 = 0.f, r1 = 0.f;
        #pragma unroll
        for (int jj = 0; jj < 8; ++jj) {
            const int row = q + 4 * jj;
            const float2* __restrict__ xp =
                reinterpret_cast<const float2*>(&xs[row][m0]);
            const float2 p0 = xp[0], p1 = xp[1], p2 = xp[2], p3 = xp[3];
            const float px0 = p0.x, px1 = p0.y, px2 = p1.x, px3 = p1.y;
            const float px4 = p2.x, px5 = p2.y, px6 = p3.x, px7 = p3.y;
            const float* __restrict__ wr = &w2s[row * 63 + i];  // (row*7+k)*9+i
            const float w0 = wr[0],  w1v = wr[9],  w2v = wr[18], w3 = wr[27];
            const float w4 = wr[36], w5 = wr[45],  w6 = wr[54];
            r0 = fmaf(px0, w0,  r0);  r1 = fmaf(px1, w0,  r1);   // k=0
            r0 = fmaf(px1, w1v, r0);  r1 = fmaf(px2, w1v, r1);   // k=1
            r0 = fmaf(px2, w2v, r0);  r1 = fmaf(px3, w2v, r1);   // k=2
            r0 = fmaf(px3, w3,  r0);  r1 = fmaf(px4, w3,  r1);   // k=3
            r0 = fmaf(px4, w4,  r0);  r1 = fmaf(px5, w4,  r1);   // k=4
            r0 = fmaf(px5, w5,  r0);  r1 = fmaf(px6, w5,  r1);   // k=5
            r0 = fmaf(px6, w6,  r0);  r1 = fmaf(px7, w6,  r1);   // k=6
        }
        // Reduce the 4 quarters (lanes q*7+mp): +14 then +7.
        r0 += __shfl_down_sync(0xFFFFFFFFu, r0, 14);
        r1 += __shfl_down_sync(0xFFFFFFFFu, r1, 14);
        r0 += __shfl_down_sync(0xFFFFFFFFu, r0, 7);
        r1 += __shfl_down_sync(0xFFFFFFFFu, r1, 7);
        if (lane < 7) {                 // q==0 lanes hold the full sums
            t4s[(m0 + 0) * 12 + i] = r0;
            t4s[(m0 + 1) * 12 + i] = r1;
        }
    }
    __syncthreads();

    // --- Phase 2 (R12 verbatim, threads 0..255): c-major, w1 in regs,
    //     t4s via broadcast LDS.128, 2 m's per 8B-aligned STG.64.
    if (tid < 256) {
        const int nout   = (n + 1) % 28;    // jnp.roll(y, +1, axis=2)
        const int mstart = mseg ? 8 : 0;
        const int ngrp   = mseg ? 3 : 4;
        float* __restrict__ orow =
            &out[((og * 128 + c) * 28 + nout) * 28 + m_base];

        #pragma unroll
        for (int gp = 0; gp < 4; ++gp) {
            if (gp < ngrp) {                // warp-uniform predicate
                float o2[2];
                #pragma unroll
                for (int qq = 0; qq < 2; ++qq) {
                    const int m = mstart + gp * 2 + qq;
                    const float4* __restrict__ tv =
                        reinterpret_cast<const float4*>(&t4s[m * 12]);
                    const float4 v0 = tv[0], v1 = tv[1], v2 = tv[2];
                    float acc = v0.x * w1r[0];
                    acc = fmaf(v0.y, w1r[1], acc);
                    acc = fmaf(v0.z, w1r[2], acc);
                    acc = fmaf(v0.w, w1r[3], acc);
                    acc = fmaf(v1.x, w1r[4], acc);
                    acc = fmaf(v1.y, w1r[5], acc);
                    acc = fmaf(v1.z, w1r[6], acc);
                    acc = fmaf(v1.w, w1r[7], acc);
                    acc = fmaf(v2.x, w1r[8], acc);
                    o2[qq] = acc;
                }
                *reinterpret_cast<float2*>(&orow[mstart + gp * 2]) =
                    make_float2(o2[0], o2[1]);
            }
        }
    }
}

extern "C" void kernel_launch(void* const* d_in, const int* in_sizes, int n_in,
                              void* d_out, int out_size) {
    const float* x  = (const float*)d_in[0];
    const float* w1 = (const float*)d_in[1];
    const float* w2 = (const float*)d_in[2];
    float* out = (float*)d_out;
    (void)in_sizes; (void)n_in; (void)out_size;

    fused_unfold_einsum_kernel<<<112, NTHREADS>>>(x, w1, w2, out);
}